// round 12
// baseline (speedup 1.0000x reference)
#include <cuda_runtime.h>
#include <cstdint>

#define NMAX 100000
#define EMAX 1000000
#define HF   64      // hidden features
#define CF   40      // classes
#define CFP  48      // padded classifier cols
#define BM   128
#define BK   16
#define XSTR 132

// Device-only scratch. Never passed from host. Zero-initialized at load;
// g_cnt is re-zeroed by k_scanC_prep each call (deterministic).
__device__ __align__(16) float g_A [(size_t)NMAX * HF];  // raw GEMM output
__device__ __align__(16) float g_B [(size_t)NMAX * HF];  // aggregation output
__device__ __align__(16) float g_dinv[NMAX];
__device__ __align__(16) int   g_cnt[NMAX];
__device__ __align__(16) int   g_rowptr[NMAX + 1];
__device__ __align__(16) int   g_cur[NMAX];
__device__ __align__(16) int   g_col[EMAX];
__device__ __align__(16) int   g_bsum[128];

// ------------------------------------------------------------- CSR build
__global__ void k_count(const int* __restrict__ ei, int E) {
    int e = (blockIdx.x * blockDim.x + threadIdx.x) * 4;
    if (e + 3 < E) {
        int4 d = *reinterpret_cast<const int4*>(ei + E + e);
        atomicAdd(&g_cnt[d.x], 1);
        atomicAdd(&g_cnt[d.y], 1);
        atomicAdd(&g_cnt[d.z], 1);
        atomicAdd(&g_cnt[d.w], 1);
    } else {
        for (int k = e; k < E; k++) atomicAdd(&g_cnt[ei[E + k]], 1);
    }
}
__global__ void k_scanA(int n) {
    __shared__ int sm[256];
    int tid  = threadIdx.x;
    int idx  = blockIdx.x * 1024 + tid * 4;
    int v0 = 0, v1 = 0, v2 = 0, v3 = 0;
    if (idx + 3 < n) {
        int4 t = *reinterpret_cast<const int4*>(&g_cnt[idx]);
        v0 = t.x; v1 = t.y; v2 = t.z; v3 = t.w;
    } else {
        if (idx     < n) v0 = g_cnt[idx];
        if (idx + 1 < n) v1 = g_cnt[idx + 1];
        if (idx + 2 < n) v2 = g_cnt[idx + 2];
        if (idx + 3 < n) v3 = g_cnt[idx + 3];
    }
    sm[tid] = v0 + v1 + v2 + v3;
    __syncthreads();
    for (int off = 1; off < 256; off <<= 1) {
        int t = (tid >= off) ? sm[tid - off] : 0;
        __syncthreads();
        sm[tid] += t;
        __syncthreads();
    }
    int excl = (tid > 0) ? sm[tid - 1] : 0;
    if (tid == 255) g_bsum[blockIdx.x] = sm[255];
    if (idx     < n) g_rowptr[idx]     = excl;
    if (idx + 1 < n) g_rowptr[idx + 1] = excl + v0;
    if (idx + 2 < n) g_rowptr[idx + 2] = excl + v0 + v1;
    if (idx + 3 < n) g_rowptr[idx + 3] = excl + v0 + v1 + v2;
}
__global__ void k_scanC_prep(int N, int E, int nb) {
    __shared__ int sb[128];
    int tid = threadIdx.x;
    if (tid < 128) sb[tid] = (tid < nb) ? g_bsum[tid] : 0;
    __syncthreads();
    for (int off = 1; off < 128; off <<= 1) {
        int t = (tid < 128 && tid >= off) ? sb[tid - off] : 0;
        __syncthreads();
        if (tid < 128) sb[tid] += t;
        __syncthreads();
    }
    int i = blockIdx.x * blockDim.x + tid;
    if (i < N) {
        int blk = i >> 10;
        int off = (blk > 0) ? sb[blk - 1] : 0;
        int rp = g_rowptr[i] + off;
        g_rowptr[i] = rp;
        g_cur[i]    = rp;
        g_dinv[i]   = rsqrtf((float)(g_cnt[i] + 1));   // +1 self loop
        g_cnt[i]    = 0;                               // ready for next call
    }
    if (i == 0) g_rowptr[N] = E;
}
__global__ void k_fill(const int* __restrict__ ei, int E) {
    int e = (blockIdx.x * blockDim.x + threadIdx.x) * 4;
    if (e + 3 < E) {
        int4 s = *reinterpret_cast<const int4*>(ei + e);
        int4 d = *reinterpret_cast<const int4*>(ei + E + e);
        int p0 = atomicAdd(&g_cur[d.x], 1);
        int p1 = atomicAdd(&g_cur[d.y], 1);
        int p2 = atomicAdd(&g_cur[d.z], 1);
        int p3 = atomicAdd(&g_cur[d.w], 1);
        g_col[p0] = s.x;
        g_col[p1] = s.y;
        g_col[p2] = s.z;
        g_col[p3] = s.w;
    } else {
        for (int k = e; k < E; k++) {
            int pos = atomicAdd(&g_cur[ei[E + k]], 1);
            g_col[pos] = ei[k];
        }
    }
}

// ------------------------------------------------------- tiled GEMM (2D reg-blocked)
// g_A[row] = in[row] @ W[K,64]   (RAW — no dinv; keeps gemm independent of CSR build)
// in = X if SRC_EXT else relu(g_B + bias) applied during tile staging.
template <int K, bool SRC_EXT>
__global__ void __launch_bounds__(256)
k_gemm(const float* __restrict__ X, const float* __restrict__ W,
       const float* __restrict__ bias, int N) {
    __shared__ float Ws[K * HF];
    __shared__ float Xs[BK * XSTR];
    __shared__ float bs[K];

    const int tid = threadIdx.x;
    {
        const float4* Wv = reinterpret_cast<const float4*>(W);
        float4* Wsv = reinterpret_cast<float4*>(Ws);
        for (int i = tid; i < K * HF / 4; i += 256) Wsv[i] = Wv[i];
        if (!SRC_EXT && tid < K) bs[tid] = bias[tid];
    }

    const int bm = blockIdx.x * BM;
    const int tc = tid & 15;
    const int tr = tid >> 4;

    const float* src = SRC_EXT ? X : (const float*)g_B;

    float acc[8][4];
#pragma unroll
    for (int i = 0; i < 8; i++)
#pragma unroll
        for (int j = 0; j < 4; j++) acc[i][j] = 0.0f;

    __syncthreads();

    for (int k0 = 0; k0 < K; k0 += BK) {
#pragma unroll
        for (int i = tid; i < BM * BK / 4; i += 256) {
            int row = i >> 2;
            int kq  = i & 3;
            int r   = bm + row;
            float4 v = make_float4(0.f, 0.f, 0.f, 0.f);
            if (r < N) {
                v = *reinterpret_cast<const float4*>(src + (size_t)r * K + k0 + kq * 4);
                if (!SRC_EXT) {
                    int kb = k0 + kq * 4;
                    v.x = fmaxf(v.x + bs[kb + 0], 0.0f);
                    v.y = fmaxf(v.y + bs[kb + 1], 0.0f);
                    v.z = fmaxf(v.z + bs[kb + 2], 0.0f);
                    v.w = fmaxf(v.w + bs[kb + 3], 0.0f);
                }
            }
            Xs[(kq * 4 + 0) * XSTR + row] = v.x;
            Xs[(kq * 4 + 1) * XSTR + row] = v.y;
            Xs[(kq * 4 + 2) * XSTR + row] = v.z;
            Xs[(kq * 4 + 3) * XSTR + row] = v.w;
        }
        __syncthreads();

#pragma unroll
        for (int kk = 0; kk < BK; kk++) {
            float4 xa = *reinterpret_cast<const float4*>(&Xs[kk * XSTR + tr * 8 + 0]);
            float4 xb = *reinterpret_cast<const float4*>(&Xs[kk * XSTR + tr * 8 + 4]);
            float4 wv = *reinterpret_cast<const float4*>(&Ws[(k0 + kk) * HF + tc * 4]);
            float xr[8] = {xa.x, xa.y, xa.z, xa.w, xb.x, xb.y, xb.z, xb.w};
#pragma unroll
            for (int i = 0; i < 8; i++) {
                acc[i][0] += xr[i] * wv.x;
                acc[i][1] += xr[i] * wv.y;
                acc[i][2] += xr[i] * wv.z;
                acc[i][3] += xr[i] * wv.w;
            }
        }
        __syncthreads();
    }

#pragma unroll
    for (int i = 0; i < 8; i++) {
        int r = bm + tr * 8 + i;
        if (r >= N) break;
        float4 v = make_float4(acc[i][0], acc[i][1], acc[i][2], acc[i][3]);
        *reinterpret_cast<float4*>(g_A + (size_t)r * HF + tc * 4) = v;
    }
}

// ------------------------------------------------------------ CSR gather
// g_B[d,:] = dinv[d] * ( dinv[d]*A[d,:] + sum_j dinv[col[j]]*A[col[j],:] )
// Half-warp per dst row; independent warps hide degree-variance latency.
__global__ void k_gather(int N) {
    int gt   = blockIdx.x * blockDim.x + threadIdx.x;
    int warp = gt >> 5;
    int lane = gt & 31;
    int d = warp * 2 + (lane >> 4);
    if (d >= N) return;
    int sub = lane & 15;

    const float4* Ap = reinterpret_cast<const float4*>(g_A);
    int beg = __ldg(&g_rowptr[d]);
    int end = __ldg(&g_rowptr[d + 1]);
    float dd = g_dinv[d];

    float4 a = Ap[(size_t)d * 16 + sub];   // self loop term (scaled by dd)
    float4 acc = make_float4(a.x * dd, a.y * dd, a.z * dd, a.w * dd);

    int j = beg;
    for (; j + 1 < end; j += 2) {
        int s0 = __ldg(&g_col[j]);
        int s1 = __ldg(&g_col[j + 1]);
        float n0 = __ldg(&g_dinv[s0]);
        float n1 = __ldg(&g_dinv[s1]);
        float4 v0 = Ap[(size_t)s0 * 16 + sub];
        float4 v1 = Ap[(size_t)s1 * 16 + sub];
        acc.x += v0.x * n0 + v1.x * n1;
        acc.y += v0.y * n0 + v1.y * n1;
        acc.z += v0.z * n0 + v1.z * n1;
        acc.w += v0.w * n0 + v1.w * n1;
    }
    if (j < end) {
        int s = __ldg(&g_col[j]);
        float n = __ldg(&g_dinv[s]);
        float4 v = Ap[(size_t)s * 16 + sub];
        acc.x += v.x * n; acc.y += v.y * n; acc.z += v.z * n; acc.w += v.w * n;
    }

    acc.x *= dd; acc.y *= dd; acc.z *= dd; acc.w *= dd;
    reinterpret_cast<float4*>(g_B)[(size_t)d * 16 + sub] = acc;
}

// ---------------------------------- tiled classifier: out = relu(B + b2) @ Wc + bc
__global__ void __launch_bounds__(192)
k_final(const float* __restrict__ b2, const float* __restrict__ Wc,
        const float* __restrict__ bc, float* __restrict__ out, int N) {
    __shared__ float Ws[HF * CFP];     // 64 x 48, zero-padded
    __shared__ float Xs[BK * XSTR];
    __shared__ float bs[HF];
    __shared__ float bcs[CFP];

    const int tid = threadIdx.x;
    for (int i = tid; i < HF * CFP; i += 192) {
        int k = i / CFP, c = i % CFP;
        Ws[i] = (c < CF) ? Wc[k * CF + c] : 0.0f;
    }
    if (tid < HF)  bs[tid]  = b2[tid];
    if (tid < CFP) bcs[tid] = (tid < CF) ? bc[tid] : 0.0f;

    const int bm = blockIdx.x * BM;
    const int tc = tid % 12;
    const int tr = tid / 12;

    float acc[8][4];
#pragma unroll
    for (int i = 0; i < 8; i++)
#pragma unroll
        for (int j = 0; j < 4; j++) acc[i][j] = 0.0f;

    __syncthreads();

    for (int k0 = 0; k0 < HF; k0 += BK) {
        for (int i = tid; i < BM * BK / 4; i += 192) {
            int row = i >> 2;
            int kq  = i & 3;
            int r   = bm + row;
            float4 v = make_float4(0.f, 0.f, 0.f, 0.f);
            if (r < N) {
                v = *reinterpret_cast<const float4*>(g_B + (size_t)r * HF + k0 + kq * 4);
                int kb = k0 + kq * 4;
                v.x = fmaxf(v.x + bs[kb + 0], 0.0f);
                v.y = fmaxf(v.y + bs[kb + 1], 0.0f);
                v.z = fmaxf(v.z + bs[kb + 2], 0.0f);
                v.w = fmaxf(v.w + bs[kb + 3], 0.0f);
            }
            Xs[(kq * 4 + 0) * XSTR + row] = v.x;
            Xs[(kq * 4 + 1) * XSTR + row] = v.y;
            Xs[(kq * 4 + 2) * XSTR + row] = v.z;
            Xs[(kq * 4 + 3) * XSTR + row] = v.w;
        }
        __syncthreads();

#pragma unroll
        for (int kk = 0; kk < BK; kk++) {
            float4 xa = *reinterpret_cast<const float4*>(&Xs[kk * XSTR + tr * 8 + 0]);
            float4 xb = *reinterpret_cast<const float4*>(&Xs[kk * XSTR + tr * 8 + 4]);
            float4 wv = *reinterpret_cast<const float4*>(&Ws[(k0 + kk) * CFP + tc * 4]);
            float xr[8] = {xa.x, xa.y, xa.z, xa.w, xb.x, xb.y, xb.z, xb.w};
#pragma unroll
            for (int i = 0; i < 8; i++) {
                acc[i][0] += xr[i] * wv.x;
                acc[i][1] += xr[i] * wv.y;
                acc[i][2] += xr[i] * wv.z;
                acc[i][3] += xr[i] * wv.w;
            }
        }
        __syncthreads();
    }

    if (tc * 4 < CF) {
#pragma unroll
        for (int i = 0; i < 8; i++) {
            int r = bm + tr * 8 + i;
            if (r >= N) break;
            float4 v = make_float4(acc[i][0] + bcs[tc * 4 + 0],
                                   acc[i][1] + bcs[tc * 4 + 1],
                                   acc[i][2] + bcs[tc * 4 + 2],
                                   acc[i][3] + bcs[tc * 4 + 3]);
            *reinterpret_cast<float4*>(out + (size_t)r * CF + tc * 4) = v;
        }
    }
}

// ------------------------------------------------------------------ launcher
extern "C" void kernel_launch(void* const* d_in, const int* in_sizes, int n_in,
                              void* d_out, int out_size) {
    const float* x  = (const float*)d_in[0];
    const int*   ei = (const int*)d_in[1];     // int32 (JAX x64-disabled)
    const float* W1 = (const float*)d_in[2];
    const float* b1 = (const float*)d_in[3];
    const float* W2 = (const float*)d_in[4];
    const float* b2 = (const float*)d_in[5];
    const float* Wc = (const float*)d_in[6];
    const float* bc = (const float*)d_in[7];
    float*       out = (float*)d_out;

    const int Hdim = in_sizes[3];             // 64
    const int Fin  = in_sizes[2] / Hdim;      // 128
    const int N    = in_sizes[0] / Fin;       // 100000
    const int E    = in_sizes[1] / 2;         // 1000000
    (void)Hdim; (void)n_in; (void)out_size;

    const int TPB = 256;
    int nBlk  = (N + TPB - 1) / TPB;
    int e4Blk = ((E + 3) / 4 + TPB - 1) / TPB;
    int gBlk  = (N + BM - 1) / BM;
    int sBlkA = (N + 1023) / 1024;
    long long gatThreads = (long long)((N + 1) / 2) * 32;
    int gatBlk = (int)((gatThreads + TPB - 1) / TPB);

    // Side stream + events, created once on the first (uncaptured) call.
    static cudaStream_t s2 = nullptr;
    static cudaEvent_t evFork = nullptr, evJoin = nullptr;
    if (s2 == nullptr) {
        cudaStreamCreateWithFlags(&s2, cudaStreamNonBlocking);
        cudaEventCreateWithFlags(&evFork, cudaEventDisableTiming);
        cudaEventCreateWithFlags(&evJoin, cudaEventDisableTiming);
    }

    // Fork: CSR build on s2, concurrent with gemm1 on the default stream.
    cudaEventRecord(evFork, 0);
    cudaStreamWaitEvent(s2, evFork, 0);

    k_count<<<e4Blk, TPB, 0, s2>>>(ei, E);
    k_scanA<<<sBlkA, 256, 0, s2>>>(N);
    k_scanC_prep<<<nBlk, TPB, 0, s2>>>(N, E, sBlkA);
    k_fill<<<e4Blk, TPB, 0, s2>>>(ei, E);
    cudaEventRecord(evJoin, s2);

    // gemm1 (CSR-independent: writes raw A)
    k_gemm<128, true><<<gBlk, TPB>>>(x, W1, nullptr, N);

    // Join: gather needs A + CSR + dinv.
    cudaStreamWaitEvent(0, evJoin, 0);

    k_gather<<<gatBlk, TPB>>>(N);
    k_gemm<64, false><<<gBlk, TPB>>>(nullptr, W2, b1, N);
    k_gather<<<gatBlk, TPB>>>(N);
    k_final<<<gBlk, 192>>>(b2, Wc, bc, out, N);
}

// round 13
// speedup vs baseline: 1.0283x; 1.0283x over previous
#include <cuda_runtime.h>
#include <cstdint>

#define NMAX 100000
#define EMAX 1000000
#define HF   64      // hidden features
#define CF   40      // classes
#define CFP  48      // padded classifier cols
#define BM   128
#define BK   16
#define XSTR 136     // Xs stride (words): 136%32=8 -> conflict-free tf32 A frags
#define WSTR 72      // Ws stride (words): 72%32=8  -> conflict-free tf32 B frags

// Device-only scratch. Never passed from host. Zero-initialized at load;
// g_cnt is re-zeroed by k_scanC_prep each call (deterministic).
__device__ __align__(16) float g_A [(size_t)NMAX * HF];  // raw GEMM output
__device__ __align__(16) float g_B [(size_t)NMAX * HF];  // aggregation output
__device__ __align__(16) float g_dinv[NMAX];
__device__ __align__(16) int   g_cnt[NMAX];
__device__ __align__(16) int   g_rowptr[NMAX + 1];
__device__ __align__(16) int   g_cur[NMAX];
__device__ __align__(16) int   g_col[EMAX];
__device__ __align__(16) int   g_bsum[128];

// ------------------------------------------------------------- CSR build
__global__ void k_count(const int* __restrict__ ei, int E) {
    int e = (blockIdx.x * blockDim.x + threadIdx.x) * 4;
    if (e + 3 < E) {
        int4 d = *reinterpret_cast<const int4*>(ei + E + e);
        atomicAdd(&g_cnt[d.x], 1);
        atomicAdd(&g_cnt[d.y], 1);
        atomicAdd(&g_cnt[d.z], 1);
        atomicAdd(&g_cnt[d.w], 1);
    } else {
        for (int k = e; k < E; k++) atomicAdd(&g_cnt[ei[E + k]], 1);
    }
}
__global__ void k_scanA(int n) {
    __shared__ int sm[256];
    int tid  = threadIdx.x;
    int idx  = blockIdx.x * 1024 + tid * 4;
    int v0 = 0, v1 = 0, v2 = 0, v3 = 0;
    if (idx + 3 < n) {
        int4 t = *reinterpret_cast<const int4*>(&g_cnt[idx]);
        v0 = t.x; v1 = t.y; v2 = t.z; v3 = t.w;
    } else {
        if (idx     < n) v0 = g_cnt[idx];
        if (idx + 1 < n) v1 = g_cnt[idx + 1];
        if (idx + 2 < n) v2 = g_cnt[idx + 2];
        if (idx + 3 < n) v3 = g_cnt[idx + 3];
    }
    sm[tid] = v0 + v1 + v2 + v3;
    __syncthreads();
    for (int off = 1; off < 256; off <<= 1) {
        int t = (tid >= off) ? sm[tid - off] : 0;
        __syncthreads();
        sm[tid] += t;
        __syncthreads();
    }
    int excl = (tid > 0) ? sm[tid - 1] : 0;
    if (tid == 255) g_bsum[blockIdx.x] = sm[255];
    if (idx     < n) g_rowptr[idx]     = excl;
    if (idx + 1 < n) g_rowptr[idx + 1] = excl + v0;
    if (idx + 2 < n) g_rowptr[idx + 2] = excl + v0 + v1;
    if (idx + 3 < n) g_rowptr[idx + 3] = excl + v0 + v1 + v2;
}
__global__ void k_scanC_prep(int N, int E, int nb) {
    __shared__ int sb[128];
    int tid = threadIdx.x;
    if (tid < 128) sb[tid] = (tid < nb) ? g_bsum[tid] : 0;
    __syncthreads();
    for (int off = 1; off < 128; off <<= 1) {
        int t = (tid < 128 && tid >= off) ? sb[tid - off] : 0;
        __syncthreads();
        if (tid < 128) sb[tid] += t;
        __syncthreads();
    }
    int i = blockIdx.x * blockDim.x + tid;
    if (i < N) {
        int blk = i >> 10;
        int off = (blk > 0) ? sb[blk - 1] : 0;
        int rp = g_rowptr[i] + off;
        g_rowptr[i] = rp;
        g_cur[i]    = rp;
        g_dinv[i]   = rsqrtf((float)(g_cnt[i] + 1));   // +1 self loop
        g_cnt[i]    = 0;                               // ready for next call
    }
    if (i == 0) g_rowptr[N] = E;
}
__global__ void k_fill(const int* __restrict__ ei, int E) {
    int e = (blockIdx.x * blockDim.x + threadIdx.x) * 4;
    if (e + 3 < E) {
        int4 s = *reinterpret_cast<const int4*>(ei + e);
        int4 d = *reinterpret_cast<const int4*>(ei + E + e);
        int p0 = atomicAdd(&g_cur[d.x], 1);
        int p1 = atomicAdd(&g_cur[d.y], 1);
        int p2 = atomicAdd(&g_cur[d.z], 1);
        int p3 = atomicAdd(&g_cur[d.w], 1);
        g_col[p0] = s.x;
        g_col[p1] = s.y;
        g_col[p2] = s.z;
        g_col[p3] = s.w;
    } else {
        for (int k = e; k < E; k++) {
            int pos = atomicAdd(&g_cur[ei[E + k]], 1);
            g_col[pos] = ei[k];
        }
    }
}

// ----------------------------------------------------------- TF32 MMA helpers
__device__ __forceinline__ uint32_t f2tf32(float v) {
    uint32_t t;
    asm("cvt.rna.tf32.f32 %0, %1;" : "=r"(t) : "f"(v));
    return t;
}
__device__ __forceinline__ void mma_tf32(float4& c, const uint32_t* a, const uint32_t* b) {
    asm volatile(
        "mma.sync.aligned.m16n8k8.row.col.f32.tf32.tf32.f32 "
        "{%0,%1,%2,%3}, {%4,%5,%6,%7}, {%8,%9}, {%0,%1,%2,%3};"
        : "+f"(c.x), "+f"(c.y), "+f"(c.z), "+f"(c.w)
        : "r"(a[0]), "r"(a[1]), "r"(a[2]), "r"(a[3]), "r"(b[0]), "r"(b[1]));
}

// -------------------------------------------------- tensor-core GEMM (tf32)
// g_A[row] = in[row] @ W[K,64]   (raw f32; dinv applied in gather)
// in = X if SRC_EXT else relu(g_B + bias) applied during tile staging.
// 8 warps in a 4x2 grid; each warp: m32 x n32 = 2x4 m16n8k8 tiles.
template <int K, bool SRC_EXT>
__global__ void __launch_bounds__(256)
k_gemm_tc(const float* __restrict__ X, const float* __restrict__ W,
          const float* __restrict__ bias, int N) {
    __shared__ uint32_t Ws[K * WSTR];   // tf32 bits, [k][n] stride 72
    __shared__ uint32_t Xs[BK * XSTR];  // tf32 bits, [k][row] stride 136
    __shared__ float bs[K];

    const int tid = threadIdx.x;
    for (int i = tid; i < K * HF; i += 256) {
        int k = i >> 6, n = i & 63;
        Ws[k * WSTR + n] = f2tf32(W[i]);
    }
    if (!SRC_EXT && tid < K) bs[tid] = bias[tid];

    const int bm   = blockIdx.x * BM;
    const int wid  = tid >> 5, lane = tid & 31;
    const int wr   = wid >> 1, wc   = wid & 1;
    const int l4   = lane >> 2, q   = lane & 3;
    const int rb   = wr * 32;           // warp row base within tile
    const int cb   = wc * 32;           // warp col base

    const float* src = SRC_EXT ? X : (const float*)g_B;

    float4 acc[2][4];
#pragma unroll
    for (int mi = 0; mi < 2; mi++)
#pragma unroll
        for (int ni = 0; ni < 4; ni++) acc[mi][ni] = make_float4(0.f, 0.f, 0.f, 0.f);

    __syncthreads();

    for (int k0 = 0; k0 < K; k0 += BK) {
        // stage X chunk [128 x 16] -> Xs[k][row], tf32-converted
#pragma unroll
        for (int i = tid; i < BM * BK / 4; i += 256) {
            int row = i >> 2;
            int kq  = i & 3;
            int r   = bm + row;
            float4 v = make_float4(0.f, 0.f, 0.f, 0.f);
            if (r < N) {
                v = *reinterpret_cast<const float4*>(src + (size_t)r * K + k0 + kq * 4);
                if (!SRC_EXT) {
                    int kb = k0 + kq * 4;
                    v.x = fmaxf(v.x + bs[kb + 0], 0.0f);
                    v.y = fmaxf(v.y + bs[kb + 1], 0.0f);
                    v.z = fmaxf(v.z + bs[kb + 2], 0.0f);
                    v.w = fmaxf(v.w + bs[kb + 3], 0.0f);
                }
            }
            Xs[(kq * 4 + 0) * XSTR + row] = f2tf32(v.x);
            Xs[(kq * 4 + 1) * XSTR + row] = f2tf32(v.y);
            Xs[(kq * 4 + 2) * XSTR + row] = f2tf32(v.z);
            Xs[(kq * 4 + 3) * XSTR + row] = f2tf32(v.w);
        }
        __syncthreads();

#pragma unroll
        for (int ks = 0; ks < BK / 8; ks++) {
            int kl = ks * 8;            // local k in Xs
            int kw = k0 + kl;           // absolute k in Ws
            uint32_t a[2][4], b[4][2];
#pragma unroll
            for (int mi = 0; mi < 2; mi++) {
                int rbase = rb + mi * 16 + l4;
                a[mi][0] = Xs[(kl + q)     * XSTR + rbase];
                a[mi][1] = Xs[(kl + q)     * XSTR + rbase + 8];
                a[mi][2] = Xs[(kl + q + 4) * XSTR + rbase];
                a[mi][3] = Xs[(kl + q + 4) * XSTR + rbase + 8];
            }
#pragma unroll
            for (int ni = 0; ni < 4; ni++) {
                int nbase = cb + ni * 8 + l4;
                b[ni][0] = Ws[(kw + q)     * WSTR + nbase];
                b[ni][1] = Ws[(kw + q + 4) * WSTR + nbase];
            }
#pragma unroll
            for (int mi = 0; mi < 2; mi++)
#pragma unroll
                for (int ni = 0; ni < 4; ni++)
                    mma_tf32(acc[mi][ni], a[mi], b[ni]);
        }
        __syncthreads();
    }

    // epilogue: c0/c1 -> (row, 2q/2q+1), c2/c3 -> (row+8, same cols)
#pragma unroll
    for (int mi = 0; mi < 2; mi++) {
        int r0 = bm + rb + mi * 16 + l4;
        int r1 = r0 + 8;
#pragma unroll
        for (int ni = 0; ni < 4; ni++) {
            int c = cb + ni * 8 + 2 * q;
            if (r0 < N)
                *reinterpret_cast<float2*>(g_A + (size_t)r0 * HF + c) =
                    make_float2(acc[mi][ni].x, acc[mi][ni].y);
            if (r1 < N)
                *reinterpret_cast<float2*>(g_A + (size_t)r1 * HF + c) =
                    make_float2(acc[mi][ni].z, acc[mi][ni].w);
        }
    }
}

// ------------------------------------------------------------ CSR gather
// g_B[d,:] = dinv[d] * ( dinv[d]*A[d,:] + sum_j dinv[col[j]]*A[col[j],:] )
__global__ void k_gather(int N) {
    int gt   = blockIdx.x * blockDim.x + threadIdx.x;
    int warp = gt >> 5;
    int lane = gt & 31;
    int d = warp * 2 + (lane >> 4);
    if (d >= N) return;
    int sub = lane & 15;

    const float4* Ap = reinterpret_cast<const float4*>(g_A);
    int beg = __ldg(&g_rowptr[d]);
    int end = __ldg(&g_rowptr[d + 1]);
    float dd = g_dinv[d];

    float4 a = Ap[(size_t)d * 16 + sub];
    float4 acc = make_float4(a.x * dd, a.y * dd, a.z * dd, a.w * dd);

    int j = beg;
    for (; j + 1 < end; j += 2) {
        int s0 = __ldg(&g_col[j]);
        int s1 = __ldg(&g_col[j + 1]);
        float n0 = __ldg(&g_dinv[s0]);
        float n1 = __ldg(&g_dinv[s1]);
        float4 v0 = Ap[(size_t)s0 * 16 + sub];
        float4 v1 = Ap[(size_t)s1 * 16 + sub];
        acc.x += v0.x * n0 + v1.x * n1;
        acc.y += v0.y * n0 + v1.y * n1;
        acc.z += v0.z * n0 + v1.z * n1;
        acc.w += v0.w * n0 + v1.w * n1;
    }
    if (j < end) {
        int s = __ldg(&g_col[j]);
        float n = __ldg(&g_dinv[s]);
        float4 v = Ap[(size_t)s * 16 + sub];
        acc.x += v.x * n; acc.y += v.y * n; acc.z += v.z * n; acc.w += v.w * n;
    }

    acc.x *= dd; acc.y *= dd; acc.z *= dd; acc.w *= dd;
    reinterpret_cast<float4*>(g_B)[(size_t)d * 16 + sub] = acc;
}

// ---------------------------------- tiled classifier: out = relu(B + b2) @ Wc + bc
__global__ void __launch_bounds__(192)
k_final(const float* __restrict__ b2, const float* __restrict__ Wc,
        const float* __restrict__ bc, float* __restrict__ out, int N) {
    __shared__ float Ws[HF * CFP];
    __shared__ float Xs[BK * 132];
    __shared__ float bs[HF];
    __shared__ float bcs[CFP];

    const int tid = threadIdx.x;
    for (int i = tid; i < HF * CFP; i += 192) {
        int k = i / CFP, c = i % CFP;
        Ws[i] = (c < CF) ? Wc[k * CF + c] : 0.0f;
    }
    if (tid < HF)  bs[tid]  = b2[tid];
    if (tid < CFP) bcs[tid] = (tid < CF) ? bc[tid] : 0.0f;

    const int bm = blockIdx.x * BM;
    const int tc = tid % 12;
    const int tr = tid / 12;

    float acc[8][4];
#pragma unroll
    for (int i = 0; i < 8; i++)
#pragma unroll
        for (int j = 0; j < 4; j++) acc[i][j] = 0.0f;

    __syncthreads();

    for (int k0 = 0; k0 < HF; k0 += BK) {
        for (int i = tid; i < BM * BK / 4; i += 192) {
            int row = i >> 2;
            int kq  = i & 3;
            int r   = bm + row;
            float4 v = make_float4(0.f, 0.f, 0.f, 0.f);
            if (r < N) {
                v = *reinterpret_cast<const float4*>(g_B + (size_t)r * HF + k0 + kq * 4);
                int kb = k0 + kq * 4;
                v.x = fmaxf(v.x + bs[kb + 0], 0.0f);
                v.y = fmaxf(v.y + bs[kb + 1], 0.0f);
                v.z = fmaxf(v.z + bs[kb + 2], 0.0f);
                v.w = fmaxf(v.w + bs[kb + 3], 0.0f);
            }
            Xs[(kq * 4 + 0) * 132 + row] = v.x;
            Xs[(kq * 4 + 1) * 132 + row] = v.y;
            Xs[(kq * 4 + 2) * 132 + row] = v.z;
            Xs[(kq * 4 + 3) * 132 + row] = v.w;
        }
        __syncthreads();

#pragma unroll
        for (int kk = 0; kk < BK; kk++) {
            float4 xa = *reinterpret_cast<const float4*>(&Xs[kk * 132 + tr * 8 + 0]);
            float4 xb = *reinterpret_cast<const float4*>(&Xs[kk * 132 + tr * 8 + 4]);
            float4 wv = *reinterpret_cast<const float4*>(&Ws[(k0 + kk) * CFP + tc * 4]);
            float xr[8] = {xa.x, xa.y, xa.z, xa.w, xb.x, xb.y, xb.z, xb.w};
#pragma unroll
            for (int i = 0; i < 8; i++) {
                acc[i][0] += xr[i] * wv.x;
                acc[i][1] += xr[i] * wv.y;
                acc[i][2] += xr[i] * wv.z;
                acc[i][3] += xr[i] * wv.w;
            }
        }
        __syncthreads();
    }

    if (tc * 4 < CF) {
#pragma unroll
        for (int i = 0; i < 8; i++) {
            int r = bm + tr * 8 + i;
            if (r >= N) break;
            float4 v = make_float4(acc[i][0] + bcs[tc * 4 + 0],
                                   acc[i][1] + bcs[tc * 4 + 1],
                                   acc[i][2] + bcs[tc * 4 + 2],
                                   acc[i][3] + bcs[tc * 4 + 3]);
            *reinterpret_cast<float4*>(out + (size_t)r * CF + tc * 4) = v;
        }
    }
}

// ------------------------------------------------------------------ launcher
extern "C" void kernel_launch(void* const* d_in, const int* in_sizes, int n_in,
                              void* d_out, int out_size) {
    const float* x  = (const float*)d_in[0];
    const int*   ei = (const int*)d_in[1];     // int32 (JAX x64-disabled)
    const float* W1 = (const float*)d_in[2];
    const float* b1 = (const float*)d_in[3];
    const float* W2 = (const float*)d_in[4];
    const float* b2 = (const float*)d_in[5];
    const float* Wc = (const float*)d_in[6];
    const float* bc = (const float*)d_in[7];
    float*       out = (float*)d_out;

    const int Hdim = in_sizes[3];             // 64
    const int Fin  = in_sizes[2] / Hdim;      // 128
    const int N    = in_sizes[0] / Fin;       // 100000
    const int E    = in_sizes[1] / 2;         // 1000000
    (void)Hdim; (void)n_in; (void)out_size;

    const int TPB = 256;
    int nBlk  = (N + TPB - 1) / TPB;
    int e4Blk = ((E + 3) / 4 + TPB - 1) / TPB;
    int gBlk  = (N + BM - 1) / BM;
    int sBlkA = (N + 1023) / 1024;
    long long gatThreads = (long long)((N + 1) / 2) * 32;
    int gatBlk = (int)((gatThreads + TPB - 1) / TPB);

    // CSR build
    k_count<<<e4Blk, TPB>>>(ei, E);
    k_scanA<<<sBlkA, 256>>>(N);
    k_scanC_prep<<<nBlk, TPB>>>(N, E, sBlkA);
    k_fill<<<e4Blk, TPB>>>(ei, E);

    // layer 1: A = x@W1 (tf32 tensor) ; B = gather(A) with dinv
    k_gemm_tc<128, true><<<gBlk, TPB>>>(x, W1, nullptr, N);
    k_gather<<<gatBlk, TPB>>>(N);

    // layer 2: A = relu(B+b1)@W2 (tf32 tensor) ; B = gather(A)
    k_gemm_tc<64, false><<<gBlk, TPB>>>(nullptr, W2, b1, N);
    k_gather<<<gatBlk, TPB>>>(N);

    // classifier (tiled, fuses relu(B + b2))
    k_final<<<gBlk, 192>>>(b2, Wc, bc, out, N);
}

// round 15
// speedup vs baseline: 1.0388x; 1.0102x over previous
#include <cuda_runtime.h>
#include <cstdint>

#define NMAX 100000
#define EMAX 1000000
#define HF   64      // hidden features
#define CF   40      // classes
#define CFP  48      // padded classifier cols
#define BM   128
#define BK   16
#define XSTR 136     // Xs stride (words): 136%32=8 -> conflict-free tf32 A frags
#define WSTR 72      // Ws stride (words): 72%32=8  -> conflict-free tf32 B frags

// Device-only scratch. Never passed from host. Zero-initialized at load;
// g_cnt is re-zeroed by k_scanC_prep each call (deterministic).
__device__ __align__(16) float g_A [(size_t)NMAX * HF];  // raw GEMM output
__device__ __align__(16) float g_B [(size_t)NMAX * HF];  // aggregation output
__device__ __align__(16) float g_dinv[NMAX];
__device__ __align__(16) int   g_cnt[NMAX];
__device__ __align__(16) int   g_rowptr[NMAX + 1];
__device__ __align__(16) int   g_eoff[EMAX];             // per-edge offset within dst row
__device__ __align__(16) int   g_col[EMAX];
__device__ __align__(16) int   g_bsum[128];

// ------------------------------------------------------------- CSR build
// count + record per-edge offset (atomicAdd return) -> fill needs no atomics
__global__ void k_count(const int* __restrict__ ei, int E) {
    int e = (blockIdx.x * blockDim.x + threadIdx.x) * 4;
    if (e + 3 < E) {
        int4 d = *reinterpret_cast<const int4*>(ei + E + e);
        int p0 = atomicAdd(&g_cnt[d.x], 1);
        int p1 = atomicAdd(&g_cnt[d.y], 1);
        int p2 = atomicAdd(&g_cnt[d.z], 1);
        int p3 = atomicAdd(&g_cnt[d.w], 1);
        *reinterpret_cast<int4*>(g_eoff + e) = make_int4(p0, p1, p2, p3);
    } else {
        for (int k = e; k < E; k++) g_eoff[k] = atomicAdd(&g_cnt[ei[E + k]], 1);
    }
}
__global__ void k_scanA(int n) {
    __shared__ int sm[256];
    int tid  = threadIdx.x;
    int idx  = blockIdx.x * 1024 + tid * 4;
    int v0 = 0, v1 = 0, v2 = 0, v3 = 0;
    if (idx + 3 < n) {
        int4 t = *reinterpret_cast<const int4*>(&g_cnt[idx]);
        v0 = t.x; v1 = t.y; v2 = t.z; v3 = t.w;
    } else {
        if (idx     < n) v0 = g_cnt[idx];
        if (idx + 1 < n) v1 = g_cnt[idx + 1];
        if (idx + 2 < n) v2 = g_cnt[idx + 2];
        if (idx + 3 < n) v3 = g_cnt[idx + 3];
    }
    sm[tid] = v0 + v1 + v2 + v3;
    __syncthreads();
    for (int off = 1; off < 256; off <<= 1) {
        int t = (tid >= off) ? sm[tid - off] : 0;
        __syncthreads();
        sm[tid] += t;
        __syncthreads();
    }
    int excl = (tid > 0) ? sm[tid - 1] : 0;
    if (tid == 255) g_bsum[blockIdx.x] = sm[255];
    if (idx     < n) g_rowptr[idx]     = excl;
    if (idx + 1 < n) g_rowptr[idx + 1] = excl + v0;
    if (idx + 2 < n) g_rowptr[idx + 2] = excl + v0 + v1;
    if (idx + 3 < n) g_rowptr[idx + 3] = excl + v0 + v1 + v2;
}
__global__ void k_scanC_prep(int N, int E, int nb) {
    __shared__ int sb[128];
    int tid = threadIdx.x;
    if (tid < 128) sb[tid] = (tid < nb) ? g_bsum[tid] : 0;
    __syncthreads();
    for (int off = 1; off < 128; off <<= 1) {
        int t = (tid < 128 && tid >= off) ? sb[tid - off] : 0;
        __syncthreads();
        if (tid < 128) sb[tid] += t;
        __syncthreads();
    }
    int i = blockIdx.x * blockDim.x + tid;
    if (i < N) {
        int blk = i >> 10;
        int off = (blk > 0) ? sb[blk - 1] : 0;
        g_rowptr[i] = g_rowptr[i] + off;
        g_dinv[i]   = rsqrtf((float)(g_cnt[i] + 1));   // +1 self loop
        g_cnt[i]    = 0;                               // ready for next call
    }
    if (i == 0) g_rowptr[N] = E;
}
// atomic-free fill: pos = rowptr[dst] + recorded offset
__global__ void k_fill(const int* __restrict__ ei, int E) {
    int e = (blockIdx.x * blockDim.x + threadIdx.x) * 4;
    if (e + 3 < E) {
        int4 s = *reinterpret_cast<const int4*>(ei + e);
        int4 d = *reinterpret_cast<const int4*>(ei + E + e);
        int4 o = *reinterpret_cast<const int4*>(g_eoff + e);
        g_col[__ldg(&g_rowptr[d.x]) + o.x] = s.x;
        g_col[__ldg(&g_rowptr[d.y]) + o.y] = s.y;
        g_col[__ldg(&g_rowptr[d.z]) + o.z] = s.z;
        g_col[__ldg(&g_rowptr[d.w]) + o.w] = s.w;
    } else {
        for (int k = e; k < E; k++)
            g_col[__ldg(&g_rowptr[ei[E + k]]) + g_eoff[k]] = ei[k];
    }
}

// ----------------------------------------------------------- TF32 MMA helpers
__device__ __forceinline__ uint32_t f2tf32(float v) {
    uint32_t t;
    asm("cvt.rna.tf32.f32 %0, %1;" : "=r"(t) : "f"(v));
    return t;
}
__device__ __forceinline__ void mma_tf32(float4& c, const uint32_t* a, const uint32_t* b) {
    asm volatile(
        "mma.sync.aligned.m16n8k8.row.col.f32.tf32.tf32.f32 "
        "{%0,%1,%2,%3}, {%4,%5,%6,%7}, {%8,%9}, {%0,%1,%2,%3};"
        : "+f"(c.x), "+f"(c.y), "+f"(c.z), "+f"(c.w)
        : "r"(a[0]), "r"(a[1]), "r"(a[2]), "r"(a[3]), "r"(b[0]), "r"(b[1]));
}

// -------------------------------------------------- tensor-core GEMM (tf32)
// g_A[row] = in[row] @ W[K,64]   (raw f32; dinv applied in gather)
// in = X if SRC_EXT else relu(g_B + bias) applied during tile staging.
// 8 warps in a 4x2 grid; each warp: m32 x n32 = 2x4 m16n8k8 tiles.
template <int K, bool SRC_EXT>
__global__ void __launch_bounds__(256)
k_gemm_tc(const float* __restrict__ X, const float* __restrict__ W,
          const float* __restrict__ bias, int N) {
    __shared__ uint32_t Ws[K * WSTR];   // tf32 bits, [k][n] stride 72
    __shared__ uint32_t Xs[BK * XSTR];  // tf32 bits, [k][row] stride 136
    __shared__ float bs[K];

    const int tid = threadIdx.x;
    for (int i = tid; i < K * HF; i += 256) {
        int k = i >> 6, n = i & 63;
        Ws[k * WSTR + n] = f2tf32(W[i]);
    }
    if (!SRC_EXT && tid < K) bs[tid] = bias[tid];

    const int bm   = blockIdx.x * BM;
    const int wid  = tid >> 5, lane = tid & 31;
    const int wr   = wid >> 1, wc   = wid & 1;
    const int l4   = lane >> 2, q   = lane & 3;
    const int rb   = wr * 32;           // warp row base within tile
    const int cb   = wc * 32;           // warp col base

    const float* src = SRC_EXT ? X : (const float*)g_B;

    float4 acc[2][4];
#pragma unroll
    for (int mi = 0; mi < 2; mi++)
#pragma unroll
        for (int ni = 0; ni < 4; ni++) acc[mi][ni] = make_float4(0.f, 0.f, 0.f, 0.f);

    __syncthreads();

    for (int k0 = 0; k0 < K; k0 += BK) {
        // stage X chunk [128 x 16] -> Xs[k][row], tf32-converted
#pragma unroll
        for (int i = tid; i < BM * BK / 4; i += 256) {
            int row = i >> 2;
            int kq  = i & 3;
            int r   = bm + row;
            float4 v = make_float4(0.f, 0.f, 0.f, 0.f);
            if (r < N) {
                v = *reinterpret_cast<const float4*>(src + (size_t)r * K + k0 + kq * 4);
                if (!SRC_EXT) {
                    int kb = k0 + kq * 4;
                    v.x = fmaxf(v.x + bs[kb + 0], 0.0f);
                    v.y = fmaxf(v.y + bs[kb + 1], 0.0f);
                    v.z = fmaxf(v.z + bs[kb + 2], 0.0f);
                    v.w = fmaxf(v.w + bs[kb + 3], 0.0f);
                }
            }
            Xs[(kq * 4 + 0) * XSTR + row] = f2tf32(v.x);
            Xs[(kq * 4 + 1) * XSTR + row] = f2tf32(v.y);
            Xs[(kq * 4 + 2) * XSTR + row] = f2tf32(v.z);
            Xs[(kq * 4 + 3) * XSTR + row] = f2tf32(v.w);
        }
        __syncthreads();

#pragma unroll
        for (int ks = 0; ks < BK / 8; ks++) {
            int kl = ks * 8;            // local k in Xs
            int kw = k0 + kl;           // absolute k in Ws
            uint32_t a[2][4], b[4][2];
#pragma unroll
            for (int mi = 0; mi < 2; mi++) {
                int rbase = rb + mi * 16 + l4;
                a[mi][0] = Xs[(kl + q)     * XSTR + rbase];
                a[mi][1] = Xs[(kl + q)     * XSTR + rbase + 8];
                a[mi][2] = Xs[(kl + q + 4) * XSTR + rbase];
                a[mi][3] = Xs[(kl + q + 4) * XSTR + rbase + 8];
            }
#pragma unroll
            for (int ni = 0; ni < 4; ni++) {
                int nbase = cb + ni * 8 + l4;
                b[ni][0] = Ws[(kw + q)     * WSTR + nbase];
                b[ni][1] = Ws[(kw + q + 4) * WSTR + nbase];
            }
#pragma unroll
            for (int mi = 0; mi < 2; mi++)
#pragma unroll
                for (int ni = 0; ni < 4; ni++)
                    mma_tf32(acc[mi][ni], a[mi], b[ni]);
        }
        __syncthreads();
    }

    // epilogue: c0/c1 -> (row, 2q/2q+1), c2/c3 -> (row+8, same cols)
#pragma unroll
    for (int mi = 0; mi < 2; mi++) {
        int r0 = bm + rb + mi * 16 + l4;
        int r1 = r0 + 8;
#pragma unroll
        for (int ni = 0; ni < 4; ni++) {
            int c = cb + ni * 8 + 2 * q;
            if (r0 < N)
                *reinterpret_cast<float2*>(g_A + (size_t)r0 * HF + c) =
                    make_float2(acc[mi][ni].x, acc[mi][ni].y);
            if (r1 < N)
                *reinterpret_cast<float2*>(g_A + (size_t)r1 * HF + c) =
                    make_float2(acc[mi][ni].z, acc[mi][ni].w);
        }
    }
}

// ------------------------------------------------------------ CSR gather
// g_B[d,:] = dinv[d] * ( dinv[d]*A[d,:] + sum_j dinv[col[j]]*A[col[j],:] )
__global__ void k_gather(int N) {
    int gt   = blockIdx.x * blockDim.x + threadIdx.x;
    int warp = gt >> 5;
    int lane = gt & 31;
    int d = warp * 2 + (lane >> 4);
    if (d >= N) return;
    int sub = lane & 15;

    const float4* Ap = reinterpret_cast<const float4*>(g_A);
    int beg = __ldg(&g_rowptr[d]);
    int end = __ldg(&g_rowptr[d + 1]);
    float dd = g_dinv[d];

    float4 a = Ap[(size_t)d * 16 + sub];
    float4 acc = make_float4(a.x * dd, a.y * dd, a.z * dd, a.w * dd);

    int j = beg;
    for (; j + 1 < end; j += 2) {
        int s0 = __ldg(&g_col[j]);
        int s1 = __ldg(&g_col[j + 1]);
        float n0 = __ldg(&g_dinv[s0]);
        float n1 = __ldg(&g_dinv[s1]);
        float4 v0 = Ap[(size_t)s0 * 16 + sub];
        float4 v1 = Ap[(size_t)s1 * 16 + sub];
        acc.x += v0.x * n0 + v1.x * n1;
        acc.y += v0.y * n0 + v1.y * n1;
        acc.z += v0.z * n0 + v1.z * n1;
        acc.w += v0.w * n0 + v1.w * n1;
    }
    if (j < end) {
        int s = __ldg(&g_col[j]);
        float n = __ldg(&g_dinv[s]);
        float4 v = Ap[(size_t)s * 16 + sub];
        acc.x += v.x * n; acc.y += v.y * n; acc.z += v.z * n; acc.w += v.w * n;
    }

    acc.x *= dd; acc.y *= dd; acc.z *= dd; acc.w *= dd;
    reinterpret_cast<float4*>(g_B)[(size_t)d * 16 + sub] = acc;
}

// ---------------------------------- tiled classifier: out = relu(B + b2) @ Wc + bc
__global__ void __launch_bounds__(192)
k_final(const float* __restrict__ b2, const float* __restrict__ Wc,
        const float* __restrict__ bc, float* __restrict__ out, int N) {
    __shared__ float Ws[HF * CFP];
    __shared__ float Xs[BK * 132];
    __shared__ float bs[HF];
    __shared__ float bcs[CFP];

    const int tid = threadIdx.x;
    for (int i = tid; i < HF * CFP; i += 192) {
        int k = i / CFP, c = i % CFP;
        Ws[i] = (c < CF) ? Wc[k * CF + c] : 0.0f;
    }
    if (tid < HF)  bs[tid]  = b2[tid];
    if (tid < CFP) bcs[tid] = (tid < CF) ? bc[tid] : 0.0f;

    const int bm = blockIdx.x * BM;
    const int tc = tid % 12;
    const int tr = tid / 12;

    float acc[8][4];
#pragma unroll
    for (int i = 0; i < 8; i++)
#pragma unroll
        for (int j = 0; j < 4; j++) acc[i][j] = 0.0f;

    __syncthreads();

    for (int k0 = 0; k0 < HF; k0 += BK) {
        for (int i = tid; i < BM * BK / 4; i += 192) {
            int row = i >> 2;
            int kq  = i & 3;
            int r   = bm + row;
            float4 v = make_float4(0.f, 0.f, 0.f, 0.f);
            if (r < N) {
                v = *reinterpret_cast<const float4*>(g_B + (size_t)r * HF + k0 + kq * 4);
                int kb = k0 + kq * 4;
                v.x = fmaxf(v.x + bs[kb + 0], 0.0f);
                v.y = fmaxf(v.y + bs[kb + 1], 0.0f);
                v.z = fmaxf(v.z + bs[kb + 2], 0.0f);
                v.w = fmaxf(v.w + bs[kb + 3], 0.0f);
            }
            Xs[(kq * 4 + 0) * 132 + row] = v.x;
            Xs[(kq * 4 + 1) * 132 + row] = v.y;
            Xs[(kq * 4 + 2) * 132 + row] = v.z;
            Xs[(kq * 4 + 3) * 132 + row] = v.w;
        }
        __syncthreads();

#pragma unroll
        for (int kk = 0; kk < BK; kk++) {
            float4 xa = *reinterpret_cast<const float4*>(&Xs[kk * 132 + tr * 8 + 0]);
            float4 xb = *reinterpret_cast<const float4*>(&Xs[kk * 132 + tr * 8 + 4]);
            float4 wv = *reinterpret_cast<const float4*>(&Ws[(k0 + kk) * CFP + tc * 4]);
            float xr[8] = {xa.x, xa.y, xa.z, xa.w, xb.x, xb.y, xb.z, xb.w};
#pragma unroll
            for (int i = 0; i < 8; i++) {
                acc[i][0] += xr[i] * wv.x;
                acc[i][1] += xr[i] * wv.y;
                acc[i][2] += xr[i] * wv.z;
                acc[i][3] += xr[i] * wv.w;
            }
        }
        __syncthreads();
    }

    if (tc * 4 < CF) {
#pragma unroll
        for (int i = 0; i < 8; i++) {
            int r = bm + tr * 8 + i;
            if (r >= N) break;
            float4 v = make_float4(acc[i][0] + bcs[tc * 4 + 0],
                                   acc[i][1] + bcs[tc * 4 + 1],
                                   acc[i][2] + bcs[tc * 4 + 2],
                                   acc[i][3] + bcs[tc * 4 + 3]);
            *reinterpret_cast<float4*>(out + (size_t)r * CF + tc * 4) = v;
        }
    }
}

// ------------------------------------------------------------------ launcher
extern "C" void kernel_launch(void* const* d_in, const int* in_sizes, int n_in,
                              void* d_out, int out_size) {
    const float* x  = (const float*)d_in[0];
    const int*   ei = (const int*)d_in[1];     // int32 (JAX x64-disabled)
    const float* W1 = (const float*)d_in[2];
    const float* b1 = (const float*)d_in[3];
    const float* W2 = (const float*)d_in[4];
    const float* b2 = (const float*)d_in[5];
    const float* Wc = (const float*)d_in[6];
    const float* bc = (const float*)d_in[7];
    float*       out = (float*)d_out;

    const int Hdim = in_sizes[3];             // 64
    const int Fin  = in_sizes[2] / Hdim;      // 128
    const int N    = in_sizes[0] / Fin;       // 100000
    const int E    = in_sizes[1] / 2;         // 1000000
    (void)Hdim; (void)n_in; (void)out_size;

    const int TPB = 256;
    int nBlk  = (N + TPB - 1) / TPB;
    int e4Blk = ((E + 3) / 4 + TPB - 1) / TPB;
    int gBlk  = (N + BM - 1) / BM;
    int sBlkA = (N + 1023) / 1024;
    long long gatThreads = (long long)((N + 1) / 2) * 32;
    int gatBlk = (int)((gatThreads + TPB - 1) / TPB);

    // CSR build (count records per-edge offsets; fill is atomic-free)
    k_count<<<e4Blk, TPB>>>(ei, E);
    k_scanA<<<sBlkA, 256>>>(N);
    k_scanC_prep<<<nBlk, TPB>>>(N, E, sBlkA);
    k_fill<<<e4Blk, TPB>>>(ei, E);

    // layer 1: A = x@W1 (tf32 mma) ; B = gather(A) with dinv
    k_gemm_tc<128, true><<<gBlk, TPB>>>(x, W1, nullptr, N);
    k_gather<<<gatBlk, TPB>>>(N);

    // layer 2: A = relu(B+b1)@W2 (tf32 mma) ; B = gather(A)
    k_gemm_tc<64, false><<<gBlk, TPB>>>(nullptr, W2, b1, N);
    k_gather<<<gatBlk, TPB>>>(N);

    // classifier (tiled, fuses relu(B + b2))
    k_final<<<gBlk, 192>>>(b2, Wc, bc, out, N);
}

// round 16
// speedup vs baseline: 1.1338x; 1.0915x over previous
#include <cuda_runtime.h>
#include <cstdint>

#define NMAX 100000
#define EMAX 1000000
#define HF   64      // hidden features
#define CF   40      // classes
#define CFP  48      // padded classifier cols
#define BM   128
#define BK   16
#define XSTR 136     // Xs stride (words): 136%32=8 -> conflict-free tf32 A frags
#define WSTR 72      // Ws stride (words): 72%32=8  -> conflict-free tf32 B frags

// Device-only scratch. Never passed from host. Zero-initialized at load;
// g_cnt is re-zeroed by k_scan each call; g_look is re-zeroed by k_count.
__device__ __align__(16) float g_A [(size_t)NMAX * HF];  // A' = (in@W)*dinv[row]
__device__ __align__(16) float g_B [(size_t)NMAX * HF];  // aggregation output
__device__ __align__(16) float g_dinv[NMAX];
__device__ __align__(16) int   g_cnt[NMAX];
__device__ __align__(16) int   g_rowptr[NMAX + 1];
__device__ __align__(16) int   g_eoff[EMAX];             // per-edge offset within dst row
__device__ __align__(16) int   g_col[EMAX];
__device__ __align__(16) unsigned long long g_look[128]; // lookback state (flag<<32|val)

// ------------------------------------------------------------- CSR build
// count + record per-edge offset; also resets lookback state + rowptr[N].
__global__ void k_count(const int* __restrict__ ei, int E, int N) {
    if (blockIdx.x == 0 && threadIdx.x < 128) g_look[threadIdx.x] = 0ull;
    if (blockIdx.x == 0 && threadIdx.x == 0) g_rowptr[N] = E;
    int e = (blockIdx.x * blockDim.x + threadIdx.x) * 4;
    if (e + 3 < E) {
        int4 d = *reinterpret_cast<const int4*>(ei + E + e);
        int p0 = atomicAdd(&g_cnt[d.x], 1);
        int p1 = atomicAdd(&g_cnt[d.y], 1);
        int p2 = atomicAdd(&g_cnt[d.z], 1);
        int p3 = atomicAdd(&g_cnt[d.w], 1);
        *reinterpret_cast<int4*>(g_eoff + e) = make_int4(p0, p1, p2, p3);
    } else {
        for (int k = e; k < E; k++) g_eoff[k] = atomicAdd(&g_cnt[ei[E + k]], 1);
    }
}

// single-pass decoupled-lookback exclusive scan of g_cnt -> g_rowptr,
// fused with dinv computation and cnt reset. 1024 items / block.
// Deterministic: integer scan result independent of arrival order; all
// blocks (98) are simultaneously resident (<=148 SMs) so lookback always
// makes progress.
__global__ void k_scan(int N, int E) {
    __shared__ int sm[256];
    __shared__ int s_prefix;
    int tid = threadIdx.x;
    int b   = blockIdx.x;
    int idx = b * 1024 + tid * 4;

    int v0 = 0, v1 = 0, v2 = 0, v3 = 0;
    if (idx + 3 < N) {
        int4 t = *reinterpret_cast<const int4*>(&g_cnt[idx]);
        v0 = t.x; v1 = t.y; v2 = t.z; v3 = t.w;
    } else {
        if (idx     < N) v0 = g_cnt[idx];
        if (idx + 1 < N) v1 = g_cnt[idx + 1];
        if (idx + 2 < N) v2 = g_cnt[idx + 2];
        if (idx + 3 < N) v3 = g_cnt[idx + 3];
    }
    sm[tid] = v0 + v1 + v2 + v3;
    __syncthreads();
    for (int off = 1; off < 256; off <<= 1) {
        int t = (tid >= off) ? sm[tid - off] : 0;
        __syncthreads();
        sm[tid] += t;
        __syncthreads();
    }
    int total = sm[255];

    if (tid == 0) {
        // publish aggregate (flag=1, value=block total) — single 64b atomic
        atomicExch(&g_look[b], (1ull << 32) | (unsigned)total);
        int prefix = 0;
        for (int p = b - 1; p >= 0; p--) {
            unsigned long long q;
            do {
                q = *(volatile unsigned long long*)&g_look[p];
            } while ((q >> 32) == 0ull);
            prefix += (int)(unsigned)q;
            if ((q >> 32) == 2ull) break;   // inclusive prefix found
        }
        // publish inclusive (flag=2, value=prefix through this block)
        atomicExch(&g_look[b], (2ull << 32) | (unsigned)(prefix + total));
        s_prefix = prefix;
    }
    __syncthreads();

    int excl = s_prefix + ((tid > 0) ? sm[tid - 1] : 0);
    if (idx < N) {
        g_rowptr[idx] = excl;
        g_dinv[idx]   = rsqrtf((float)(v0 + 1));
        g_cnt[idx]    = 0;
    }
    if (idx + 1 < N) {
        g_rowptr[idx + 1] = excl + v0;
        g_dinv[idx + 1]   = rsqrtf((float)(v1 + 1));
        g_cnt[idx + 1]    = 0;
    }
    if (idx + 2 < N) {
        g_rowptr[idx + 2] = excl + v0 + v1;
        g_dinv[idx + 2]   = rsqrtf((float)(v2 + 1));
        g_cnt[idx + 2]    = 0;
    }
    if (idx + 3 < N) {
        g_rowptr[idx + 3] = excl + v0 + v1 + v2;
        g_dinv[idx + 3]   = rsqrtf((float)(v3 + 1));
        g_cnt[idx + 3]    = 0;
    }
}

// atomic-free fill: pos = rowptr[dst] + recorded offset
__global__ void k_fill(const int* __restrict__ ei, int E) {
    int e = (blockIdx.x * blockDim.x + threadIdx.x) * 4;
    if (e + 3 < E) {
        int4 s = *reinterpret_cast<const int4*>(ei + e);
        int4 d = *reinterpret_cast<const int4*>(ei + E + e);
        int4 o = *reinterpret_cast<const int4*>(g_eoff + e);
        g_col[__ldg(&g_rowptr[d.x]) + o.x] = s.x;
        g_col[__ldg(&g_rowptr[d.y]) + o.y] = s.y;
        g_col[__ldg(&g_rowptr[d.z]) + o.z] = s.z;
        g_col[__ldg(&g_rowptr[d.w]) + o.w] = s.w;
    } else {
        for (int k = e; k < E; k++)
            g_col[__ldg(&g_rowptr[ei[E + k]]) + g_eoff[k]] = ei[k];
    }
}

// ----------------------------------------------------------- TF32 MMA helpers
__device__ __forceinline__ uint32_t f2tf32(float v) {
    uint32_t t;
    asm("cvt.rna.tf32.f32 %0, %1;" : "=r"(t) : "f"(v));
    return t;
}
__device__ __forceinline__ void mma_tf32(float4& c, const uint32_t* a, const uint32_t* b) {
    asm volatile(
        "mma.sync.aligned.m16n8k8.row.col.f32.tf32.tf32.f32 "
        "{%0,%1,%2,%3}, {%4,%5,%6,%7}, {%8,%9}, {%0,%1,%2,%3};"
        : "+f"(c.x), "+f"(c.y), "+f"(c.z), "+f"(c.w)
        : "r"(a[0]), "r"(a[1]), "r"(a[2]), "r"(a[3]), "r"(b[0]), "r"(b[1]));
}

// -------------------------------------------------- tensor-core GEMM (tf32)
// g_A[row] = (in[row] @ W[K,64]) * dinv[row]   (A' form)
// in = X if SRC_EXT else relu(g_B + bias) applied during tile staging.
template <int K, bool SRC_EXT>
__global__ void __launch_bounds__(256)
k_gemm_tc(const float* __restrict__ X, const float* __restrict__ W,
          const float* __restrict__ bias, int N) {
    __shared__ uint32_t Ws[K * WSTR];
    __shared__ uint32_t Xs[BK * XSTR];
    __shared__ float bs[K];

    const int tid = threadIdx.x;
    for (int i = tid; i < K * HF; i += 256) {
        int k = i >> 6, n = i & 63;
        Ws[k * WSTR + n] = f2tf32(W[i]);
    }
    if (!SRC_EXT && tid < K) bs[tid] = bias[tid];

    const int bm   = blockIdx.x * BM;
    const int wid  = tid >> 5, lane = tid & 31;
    const int wr   = wid >> 1, wc   = wid & 1;
    const int l4   = lane >> 2, q   = lane & 3;
    const int rb   = wr * 32;
    const int cb   = wc * 32;

    const float* src = SRC_EXT ? X : (const float*)g_B;

    float4 acc[2][4];
#pragma unroll
    for (int mi = 0; mi < 2; mi++)
#pragma unroll
        for (int ni = 0; ni < 4; ni++) acc[mi][ni] = make_float4(0.f, 0.f, 0.f, 0.f);

    __syncthreads();

    for (int k0 = 0; k0 < K; k0 += BK) {
#pragma unroll
        for (int i = tid; i < BM * BK / 4; i += 256) {
            int row = i >> 2;
            int kq  = i & 3;
            int r   = bm + row;
            float4 v = make_float4(0.f, 0.f, 0.f, 0.f);
            if (r < N) {
                v = *reinterpret_cast<const float4*>(src + (size_t)r * K + k0 + kq * 4);
                if (!SRC_EXT) {
                    int kb = k0 + kq * 4;
                    v.x = fmaxf(v.x + bs[kb + 0], 0.0f);
                    v.y = fmaxf(v.y + bs[kb + 1], 0.0f);
                    v.z = fmaxf(v.z + bs[kb + 2], 0.0f);
                    v.w = fmaxf(v.w + bs[kb + 3], 0.0f);
                }
            }
            Xs[(kq * 4 + 0) * XSTR + row] = f2tf32(v.x);
            Xs[(kq * 4 + 1) * XSTR + row] = f2tf32(v.y);
            Xs[(kq * 4 + 2) * XSTR + row] = f2tf32(v.z);
            Xs[(kq * 4 + 3) * XSTR + row] = f2tf32(v.w);
        }
        __syncthreads();

#pragma unroll
        for (int ks = 0; ks < BK / 8; ks++) {
            int kl = ks * 8;
            int kw = k0 + kl;
            uint32_t a[2][4], b[4][2];
#pragma unroll
            for (int mi = 0; mi < 2; mi++) {
                int rbase = rb + mi * 16 + l4;
                a[mi][0] = Xs[(kl + q)     * XSTR + rbase];
                a[mi][1] = Xs[(kl + q)     * XSTR + rbase + 8];
                a[mi][2] = Xs[(kl + q + 4) * XSTR + rbase];
                a[mi][3] = Xs[(kl + q + 4) * XSTR + rbase + 8];
            }
#pragma unroll
            for (int ni = 0; ni < 4; ni++) {
                int nbase = cb + ni * 8 + l4;
                b[ni][0] = Ws[(kw + q)     * WSTR + nbase];
                b[ni][1] = Ws[(kw + q + 4) * WSTR + nbase];
            }
#pragma unroll
            for (int mi = 0; mi < 2; mi++)
#pragma unroll
                for (int ni = 0; ni < 4; ni++)
                    mma_tf32(acc[mi][ni], a[mi], b[ni]);
        }
        __syncthreads();
    }

    // epilogue: scale rows by dinv, store A'
#pragma unroll
    for (int mi = 0; mi < 2; mi++) {
        int r0 = bm + rb + mi * 16 + l4;
        int r1 = r0 + 8;
        float d0 = (r0 < N) ? g_dinv[r0] : 0.0f;
        float d1 = (r1 < N) ? g_dinv[r1] : 0.0f;
#pragma unroll
        for (int ni = 0; ni < 4; ni++) {
            int c = cb + ni * 8 + 2 * q;
            if (r0 < N)
                *reinterpret_cast<float2*>(g_A + (size_t)r0 * HF + c) =
                    make_float2(acc[mi][ni].x * d0, acc[mi][ni].y * d0);
            if (r1 < N)
                *reinterpret_cast<float2*>(g_A + (size_t)r1 * HF + c) =
                    make_float2(acc[mi][ni].z * d1, acc[mi][ni].w * d1);
        }
    }
}

// ------------------------------------------------------------ CSR gather
// g_B[d,:] = dinv[d] * ( A'[d,:] + sum_j A'[col[j],:] )
// Half-warp per dst row; 4-deep neighbor unroll for MLP.
__global__ void k_gather(int N) {
    int gt   = blockIdx.x * blockDim.x + threadIdx.x;
    int warp = gt >> 5;
    int lane = gt & 31;
    int d = warp * 2 + (lane >> 4);
    if (d >= N) return;
    int sub = lane & 15;

    const float4* Ap = reinterpret_cast<const float4*>(g_A);
    int beg = __ldg(&g_rowptr[d]);
    int end = __ldg(&g_rowptr[d + 1]);

    float4 acc = Ap[(size_t)d * 16 + sub];   // self-loop term (already * dinv[d])

    int j = beg;
    for (; j + 3 < end; j += 4) {
        int s0 = __ldg(&g_col[j]);
        int s1 = __ldg(&g_col[j + 1]);
        int s2 = __ldg(&g_col[j + 2]);
        int s3 = __ldg(&g_col[j + 3]);
        float4 v0 = Ap[(size_t)s0 * 16 + sub];
        float4 v1 = Ap[(size_t)s1 * 16 + sub];
        float4 v2 = Ap[(size_t)s2 * 16 + sub];
        float4 v3 = Ap[(size_t)s3 * 16 + sub];
        acc.x += (v0.x + v1.x) + (v2.x + v3.x);
        acc.y += (v0.y + v1.y) + (v2.y + v3.y);
        acc.z += (v0.z + v1.z) + (v2.z + v3.z);
        acc.w += (v0.w + v1.w) + (v2.w + v3.w);
    }
    for (; j < end; j++) {
        int s = __ldg(&g_col[j]);
        float4 v = Ap[(size_t)s * 16 + sub];
        acc.x += v.x; acc.y += v.y; acc.z += v.z; acc.w += v.w;
    }

    float dd = g_dinv[d];
    acc.x *= dd; acc.y *= dd; acc.z *= dd; acc.w *= dd;
    reinterpret_cast<float4*>(g_B)[(size_t)d * 16 + sub] = acc;
}

// ---------------------------------- tiled classifier: out = relu(B + b2) @ Wc + bc
__global__ void __launch_bounds__(192)
k_final(const float* __restrict__ b2, const float* __restrict__ Wc,
        const float* __restrict__ bc, float* __restrict__ out, int N) {
    __shared__ float Ws[HF * CFP];
    __shared__ float Xs[BK * 132];
    __shared__ float bs[HF];
    __shared__ float bcs[CFP];

    const int tid = threadIdx.x;
    for (int i = tid; i < HF * CFP; i += 192) {
        int k = i / CFP, c = i % CFP;
        Ws[i] = (c < CF) ? Wc[k * CF + c] : 0.0f;
    }
    if (tid < HF)  bs[tid]  = b2[tid];
    if (tid < CFP) bcs[tid] = (tid < CF) ? bc[tid] : 0.0f;

    const int bm = blockIdx.x * BM;
    const int tc = tid % 12;
    const int tr = tid / 12;

    float acc[8][4];
#pragma unroll
    for (int i = 0; i < 8; i++)
#pragma unroll
        for (int j = 0; j < 4; j++) acc[i][j] = 0.0f;

    __syncthreads();

    for (int k0 = 0; k0 < HF; k0 += BK) {
        for (int i = tid; i < BM * BK / 4; i += 192) {
            int row = i >> 2;
            int kq  = i & 3;
            int r   = bm + row;
            float4 v = make_float4(0.f, 0.f, 0.f, 0.f);
            if (r < N) {
                v = *reinterpret_cast<const float4*>(g_B + (size_t)r * HF + k0 + kq * 4);
                int kb = k0 + kq * 4;
                v.x = fmaxf(v.x + bs[kb + 0], 0.0f);
                v.y = fmaxf(v.y + bs[kb + 1], 0.0f);
                v.z = fmaxf(v.z + bs[kb + 2], 0.0f);
                v.w = fmaxf(v.w + bs[kb + 3], 0.0f);
            }
            Xs[(kq * 4 + 0) * 132 + row] = v.x;
            Xs[(kq * 4 + 1) * 132 + row] = v.y;
            Xs[(kq * 4 + 2) * 132 + row] = v.z;
            Xs[(kq * 4 + 3) * 132 + row] = v.w;
        }
        __syncthreads();

#pragma unroll
        for (int kk = 0; kk < BK; kk++) {
            float4 xa = *reinterpret_cast<const float4*>(&Xs[kk * 132 + tr * 8 + 0]);
            float4 xb = *reinterpret_cast<const float4*>(&Xs[kk * 132 + tr * 8 + 4]);
            float4 wv = *reinterpret_cast<const float4*>(&Ws[(k0 + kk) * CFP + tc * 4]);
            float xr[8] = {xa.x, xa.y, xa.z, xa.w, xb.x, xb.y, xb.z, xb.w};
#pragma unroll
            for (int i = 0; i < 8; i++) {
                acc[i][0] += xr[i] * wv.x;
                acc[i][1] += xr[i] * wv.y;
                acc[i][2] += xr[i] * wv.z;
                acc[i][3] += xr[i] * wv.w;
            }
        }
        __syncthreads();
    }

    if (tc * 4 < CF) {
#pragma unroll
        for (int i = 0; i < 8; i++) {
            int r = bm + tr * 8 + i;
            if (r >= N) break;
            float4 v = make_float4(acc[i][0] + bcs[tc * 4 + 0],
                                   acc[i][1] + bcs[tc * 4 + 1],
                                   acc[i][2] + bcs[tc * 4 + 2],
                                   acc[i][3] + bcs[tc * 4 + 3]);
            *reinterpret_cast<float4*>(out + (size_t)r * CF + tc * 4) = v;
        }
    }
}

// ------------------------------------------------------------------ launcher
extern "C" void kernel_launch(void* const* d_in, const int* in_sizes, int n_in,
                              void* d_out, int out_size) {
    const float* x  = (const float*)d_in[0];
    const int*   ei = (const int*)d_in[1];     // int32 (JAX x64-disabled)
    const float* W1 = (const float*)d_in[2];
    const float* b1 = (const float*)d_in[3];
    const float* W2 = (const float*)d_in[4];
    const float* b2 = (const float*)d_in[5];
    const float* Wc = (const float*)d_in[6];
    const float* bc = (const float*)d_in[7];
    float*       out = (float*)d_out;

    const int Hdim = in_sizes[3];             // 64
    const int Fin  = in_sizes[2] / Hdim;      // 128
    const int N    = in_sizes[0] / Fin;       // 100000
    const int E    = in_sizes[1] / 2;         // 1000000
    (void)Hdim; (void)n_in; (void)out_size;

    const int TPB = 256;
    int e4Blk = ((E + 3) / 4 + TPB - 1) / TPB;
    int gBlk  = (N + BM - 1) / BM;
    int sBlk  = (N + 1023) / 1024;            // 98 (all resident -> lookback safe)
    long long gatThreads = (long long)((N + 1) / 2) * 32;
    int gatBlk = (int)((gatThreads + TPB - 1) / TPB);

    // CSR build: 3 launches (count -> fused lookback scan -> atomic-free fill)
    k_count<<<e4Blk, TPB>>>(ei, E, N);
    k_scan<<<sBlk, 256>>>(N, E);
    k_fill<<<e4Blk, TPB>>>(ei, E);

    // layer 1: A' = (x@W1)*dinv ; B = gather(A')
    k_gemm_tc<128, true><<<gBlk, TPB>>>(x, W1, nullptr, N);
    k_gather<<<gatBlk, TPB>>>(N);

    // layer 2: A' = (relu(B+b1)@W2)*dinv ; B = gather(A')
    k_gemm_tc<64, false><<<gBlk, TPB>>>(nullptr, W2, b1, N);
    k_gather<<<gatBlk, TPB>>>(N);

    // classifier (tiled, fuses relu(B + b2))
    k_final<<<gBlk, 192>>>(b2, Wc, bc, out, N);
}

// round 17
// speedup vs baseline: 1.1386x; 1.0042x over previous
#include <cuda_runtime.h>
#include <cuda_fp16.h>
#include <cstdint>

#define NMAX 100000
#define EMAX 1000000
#define HF   64      // hidden features
#define CF   40      // classes
#define CFP  48      // padded classifier cols
#define BM   128
#define BK   16
#define XSTR 136     // Xs stride (words): 136%32=8 -> conflict-free tf32 A frags
#define WSTR 72      // Ws stride (words): 72%32=8  -> conflict-free tf32 B frags

// Device-only scratch. Never passed from host. Zero-initialized at load;
// g_cnt is re-zeroed by k_scan each call; g_look is re-zeroed by k_count.
__device__ __align__(16) __half g_A [(size_t)NMAX * HF]; // A' = (in@W)*dinv[row], fp16
__device__ __align__(16) float  g_B [(size_t)NMAX * HF]; // aggregation output, fp32
__device__ __align__(16) float  g_dinv[NMAX];
__device__ __align__(16) int    g_cnt[NMAX];
__device__ __align__(16) int    g_rowptr[NMAX + 1];
__device__ __align__(16) int    g_eoff[EMAX];            // per-edge offset within dst row
__device__ __align__(16) int    g_col[EMAX];
__device__ __align__(16) unsigned long long g_look[128]; // lookback state (flag<<32|val)

// ------------------------------------------------------------- CSR build
__global__ void k_count(const int* __restrict__ ei, int E, int N) {
    if (blockIdx.x == 0 && threadIdx.x < 128) g_look[threadIdx.x] = 0ull;
    if (blockIdx.x == 0 && threadIdx.x == 0) g_rowptr[N] = E;
    int e = (blockIdx.x * blockDim.x + threadIdx.x) * 4;
    if (e + 3 < E) {
        int4 d = *reinterpret_cast<const int4*>(ei + E + e);
        int p0 = atomicAdd(&g_cnt[d.x], 1);
        int p1 = atomicAdd(&g_cnt[d.y], 1);
        int p2 = atomicAdd(&g_cnt[d.z], 1);
        int p3 = atomicAdd(&g_cnt[d.w], 1);
        *reinterpret_cast<int4*>(g_eoff + e) = make_int4(p0, p1, p2, p3);
    } else {
        for (int k = e; k < E; k++) g_eoff[k] = atomicAdd(&g_cnt[ei[E + k]], 1);
    }
}

// single-pass decoupled-lookback exclusive scan (fused dinv + cnt reset)
__global__ void k_scan(int N, int E) {
    __shared__ int sm[256];
    __shared__ int s_prefix;
    int tid = threadIdx.x;
    int b   = blockIdx.x;
    int idx = b * 1024 + tid * 4;

    int v0 = 0, v1 = 0, v2 = 0, v3 = 0;
    if (idx + 3 < N) {
        int4 t = *reinterpret_cast<const int4*>(&g_cnt[idx]);
        v0 = t.x; v1 = t.y; v2 = t.z; v3 = t.w;
    } else {
        if (idx     < N) v0 = g_cnt[idx];
        if (idx + 1 < N) v1 = g_cnt[idx + 1];
        if (idx + 2 < N) v2 = g_cnt[idx + 2];
        if (idx + 3 < N) v3 = g_cnt[idx + 3];
    }
    sm[tid] = v0 + v1 + v2 + v3;
    __syncthreads();
    for (int off = 1; off < 256; off <<= 1) {
        int t = (tid >= off) ? sm[tid - off] : 0;
        __syncthreads();
        sm[tid] += t;
        __syncthreads();
    }
    int total = sm[255];

    if (tid == 0) {
        atomicExch(&g_look[b], (1ull << 32) | (unsigned)total);
        int prefix = 0;
        for (int p = b - 1; p >= 0; p--) {
            unsigned long long q;
            do {
                q = *(volatile unsigned long long*)&g_look[p];
            } while ((q >> 32) == 0ull);
            prefix += (int)(unsigned)q;
            if ((q >> 32) == 2ull) break;
        }
        atomicExch(&g_look[b], (2ull << 32) | (unsigned)(prefix + total));
        s_prefix = prefix;
    }
    __syncthreads();

    int excl = s_prefix + ((tid > 0) ? sm[tid - 1] : 0);
    if (idx < N)     { g_rowptr[idx]     = excl;               g_dinv[idx]     = rsqrtf((float)(v0 + 1)); g_cnt[idx]     = 0; }
    if (idx + 1 < N) { g_rowptr[idx + 1] = excl + v0;          g_dinv[idx + 1] = rsqrtf((float)(v1 + 1)); g_cnt[idx + 1] = 0; }
    if (idx + 2 < N) { g_rowptr[idx + 2] = excl + v0 + v1;     g_dinv[idx + 2] = rsqrtf((float)(v2 + 1)); g_cnt[idx + 2] = 0; }
    if (idx + 3 < N) { g_rowptr[idx + 3] = excl + v0 + v1 + v2; g_dinv[idx + 3] = rsqrtf((float)(v3 + 1)); g_cnt[idx + 3] = 0; }
}

// atomic-free fill: pos = rowptr[dst] + recorded offset
__global__ void k_fill(const int* __restrict__ ei, int E) {
    int e = (blockIdx.x * blockDim.x + threadIdx.x) * 4;
    if (e + 3 < E) {
        int4 s = *reinterpret_cast<const int4*>(ei + e);
        int4 d = *reinterpret_cast<const int4*>(ei + E + e);
        int4 o = *reinterpret_cast<const int4*>(g_eoff + e);
        g_col[__ldg(&g_rowptr[d.x]) + o.x] = s.x;
        g_col[__ldg(&g_rowptr[d.y]) + o.y] = s.y;
        g_col[__ldg(&g_rowptr[d.z]) + o.z] = s.z;
        g_col[__ldg(&g_rowptr[d.w]) + o.w] = s.w;
    } else {
        for (int k = e; k < E; k++)
            g_col[__ldg(&g_rowptr[ei[E + k]]) + g_eoff[k]] = ei[k];
    }
}

// ----------------------------------------------------------- TF32 MMA helpers
__device__ __forceinline__ uint32_t f2tf32(float v) {
    uint32_t t;
    asm("cvt.rna.tf32.f32 %0, %1;" : "=r"(t) : "f"(v));
    return t;
}
__device__ __forceinline__ void mma_tf32(float4& c, const uint32_t* a, const uint32_t* b) {
    asm volatile(
        "mma.sync.aligned.m16n8k8.row.col.f32.tf32.tf32.f32 "
        "{%0,%1,%2,%3}, {%4,%5,%6,%7}, {%8,%9}, {%0,%1,%2,%3};"
        : "+f"(c.x), "+f"(c.y), "+f"(c.z), "+f"(c.w)
        : "r"(a[0]), "r"(a[1]), "r"(a[2]), "r"(a[3]), "r"(b[0]), "r"(b[1]));
}

// -------------------------------------------------- tensor-core GEMM (tf32)
// g_A[row] = half( (in[row] @ W[K,64]) * dinv[row] )   (A' form, fp16 storage)
// in = X if SRC_EXT else relu(g_B + bias) applied during tile staging.
template <int K, bool SRC_EXT>
__global__ void __launch_bounds__(256)
k_gemm_tc(const float* __restrict__ X, const float* __restrict__ W,
          const float* __restrict__ bias, int N) {
    __shared__ uint32_t Ws[K * WSTR];
    __shared__ uint32_t Xs[BK * XSTR];
    __shared__ float bs[K];

    const int tid = threadIdx.x;
    for (int i = tid; i < K * HF; i += 256) {
        int k = i >> 6, n = i & 63;
        Ws[k * WSTR + n] = f2tf32(W[i]);
    }
    if (!SRC_EXT && tid < K) bs[tid] = bias[tid];

    const int bm   = blockIdx.x * BM;
    const int wid  = tid >> 5, lane = tid & 31;
    const int wr   = wid >> 1, wc   = wid & 1;
    const int l4   = lane >> 2, q   = lane & 3;
    const int rb   = wr * 32;
    const int cb   = wc * 32;

    const float* src = SRC_EXT ? X : (const float*)g_B;

    float4 acc[2][4];
#pragma unroll
    for (int mi = 0; mi < 2; mi++)
#pragma unroll
        for (int ni = 0; ni < 4; ni++) acc[mi][ni] = make_float4(0.f, 0.f, 0.f, 0.f);

    __syncthreads();

    for (int k0 = 0; k0 < K; k0 += BK) {
#pragma unroll
        for (int i = tid; i < BM * BK / 4; i += 256) {
            int row = i >> 2;
            int kq  = i & 3;
            int r   = bm + row;
            float4 v = make_float4(0.f, 0.f, 0.f, 0.f);
            if (r < N) {
                v = *reinterpret_cast<const float4*>(src + (size_t)r * K + k0 + kq * 4);
                if (!SRC_EXT) {
                    int kb = k0 + kq * 4;
                    v.x = fmaxf(v.x + bs[kb + 0], 0.0f);
                    v.y = fmaxf(v.y + bs[kb + 1], 0.0f);
                    v.z = fmaxf(v.z + bs[kb + 2], 0.0f);
                    v.w = fmaxf(v.w + bs[kb + 3], 0.0f);
                }
            }
            Xs[(kq * 4 + 0) * XSTR + row] = f2tf32(v.x);
            Xs[(kq * 4 + 1) * XSTR + row] = f2tf32(v.y);
            Xs[(kq * 4 + 2) * XSTR + row] = f2tf32(v.z);
            Xs[(kq * 4 + 3) * XSTR + row] = f2tf32(v.w);
        }
        __syncthreads();

#pragma unroll
        for (int ks = 0; ks < BK / 8; ks++) {
            int kl = ks * 8;
            int kw = k0 + kl;
            uint32_t a[2][4], b[4][2];
#pragma unroll
            for (int mi = 0; mi < 2; mi++) {
                int rbase = rb + mi * 16 + l4;
                a[mi][0] = Xs[(kl + q)     * XSTR + rbase];
                a[mi][1] = Xs[(kl + q)     * XSTR + rbase + 8];
                a[mi][2] = Xs[(kl + q + 4) * XSTR + rbase];
                a[mi][3] = Xs[(kl + q + 4) * XSTR + rbase + 8];
            }
#pragma unroll
            for (int ni = 0; ni < 4; ni++) {
                int nbase = cb + ni * 8 + l4;
                b[ni][0] = Ws[(kw + q)     * WSTR + nbase];
                b[ni][1] = Ws[(kw + q + 4) * WSTR + nbase];
            }
#pragma unroll
            for (int mi = 0; mi < 2; mi++)
#pragma unroll
                for (int ni = 0; ni < 4; ni++)
                    mma_tf32(acc[mi][ni], a[mi], b[ni]);
        }
        __syncthreads();
    }

    // epilogue: scale rows by dinv, convert to fp16, store A' (half2 per pair)
#pragma unroll
    for (int mi = 0; mi < 2; mi++) {
        int r0 = bm + rb + mi * 16 + l4;
        int r1 = r0 + 8;
        float d0 = (r0 < N) ? g_dinv[r0] : 0.0f;
        float d1 = (r1 < N) ? g_dinv[r1] : 0.0f;
#pragma unroll
        for (int ni = 0; ni < 4; ni++) {
            int c = cb + ni * 8 + 2 * q;
            if (r0 < N)
                *reinterpret_cast<__half2*>(g_A + (size_t)r0 * HF + c) =
                    __floats2half2_rn(acc[mi][ni].x * d0, acc[mi][ni].y * d0);
            if (r1 < N)
                *reinterpret_cast<__half2*>(g_A + (size_t)r1 * HF + c) =
                    __floats2half2_rn(acc[mi][ni].z * d1, acc[mi][ni].w * d1);
        }
    }
}

// ------------------------------------------------------------ CSR gather
// g_B[d,:] = dinv[d] * ( A'[d,:] + sum_j A'[col[j],:] )   (A' fp16, acc fp32)
// Half-warp per dst row; each lane covers 4 cols = one uint2 (8B).
__device__ __forceinline__ float4 h4_to_f4(uint2 u) {
    float2 fa = __half22float2(*reinterpret_cast<__half2*>(&u.x));
    float2 fb = __half22float2(*reinterpret_cast<__half2*>(&u.y));
    return make_float4(fa.x, fa.y, fb.x, fb.y);
}
__global__ void k_gather(int N) {
    int gt   = blockIdx.x * blockDim.x + threadIdx.x;
    int warp = gt >> 5;
    int lane = gt & 31;
    int d = warp * 2 + (lane >> 4);
    if (d >= N) return;
    int sub = lane & 15;

    const uint2* Ap = reinterpret_cast<const uint2*>(g_A);  // 16 uint2 per row
    int beg = __ldg(&g_rowptr[d]);
    int end = __ldg(&g_rowptr[d + 1]);

    float4 acc = h4_to_f4(Ap[(size_t)d * 16 + sub]);   // self-loop term

    int j = beg;
    for (; j + 3 < end; j += 4) {
        int s0 = __ldg(&g_col[j]);
        int s1 = __ldg(&g_col[j + 1]);
        int s2 = __ldg(&g_col[j + 2]);
        int s3 = __ldg(&g_col[j + 3]);
        float4 v0 = h4_to_f4(Ap[(size_t)s0 * 16 + sub]);
        float4 v1 = h4_to_f4(Ap[(size_t)s1 * 16 + sub]);
        float4 v2 = h4_to_f4(Ap[(size_t)s2 * 16 + sub]);
        float4 v3 = h4_to_f4(Ap[(size_t)s3 * 16 + sub]);
        acc.x += (v0.x + v1.x) + (v2.x + v3.x);
        acc.y += (v0.y + v1.y) + (v2.y + v3.y);
        acc.z += (v0.z + v1.z) + (v2.z + v3.z);
        acc.w += (v0.w + v1.w) + (v2.w + v3.w);
    }
    for (; j < end; j++) {
        int s = __ldg(&g_col[j]);
        float4 v = h4_to_f4(Ap[(size_t)s * 16 + sub]);
        acc.x += v.x; acc.y += v.y; acc.z += v.z; acc.w += v.w;
    }

    float dd = g_dinv[d];
    acc.x *= dd; acc.y *= dd; acc.z *= dd; acc.w *= dd;
    reinterpret_cast<float4*>(g_B)[(size_t)d * 16 + sub] = acc;
}

// ---------------------------------- tiled classifier: out = relu(B + b2) @ Wc + bc
__global__ void __launch_bounds__(192)
k_final(const float* __restrict__ b2, const float* __restrict__ Wc,
        const float* __restrict__ bc, float* __restrict__ out, int N) {
    __shared__ float Ws[HF * CFP];
    __shared__ float Xs[BK * 132];
    __shared__ float bs[HF];
    __shared__ float bcs[CFP];

    const int tid = threadIdx.x;
    for (int i = tid; i < HF * CFP; i += 192) {
        int k = i / CFP, c = i % CFP;
        Ws[i] = (c < CF) ? Wc[k * CF + c] : 0.0f;
    }
    if (tid < HF)  bs[tid]  = b2[tid];
    if (tid < CFP) bcs[tid] = (tid < CF) ? bc[tid] : 0.0f;

    const int bm = blockIdx.x * BM;
    const int tc = tid % 12;
    const int tr = tid / 12;

    float acc[8][4];
#pragma unroll
    for (int i = 0; i < 8; i++)
#pragma unroll
        for (int j = 0; j < 4; j++) acc[i][j] = 0.0f;

    __syncthreads();

    for (int k0 = 0; k0 < HF; k0 += BK) {
        for (int i = tid; i < BM * BK / 4; i += 192) {
            int row = i >> 2;
            int kq  = i & 3;
            int r   = bm + row;
            float4 v = make_float4(0.f, 0.f, 0.f, 0.f);
            if (r < N) {
                v = *reinterpret_cast<const float4*>(g_B + (size_t)r * HF + k0 + kq * 4);
                int kb = k0 + kq * 4;
                v.x = fmaxf(v.x + bs[kb + 0], 0.0f);
                v.y = fmaxf(v.y + bs[kb + 1], 0.0f);
                v.z = fmaxf(v.z + bs[kb + 2], 0.0f);
                v.w = fmaxf(v.w + bs[kb + 3], 0.0f);
            }
            Xs[(kq * 4 + 0) * 132 + row] = v.x;
            Xs[(kq * 4 + 1) * 132 + row] = v.y;
            Xs[(kq * 4 + 2) * 132 + row] = v.z;
            Xs[(kq * 4 + 3) * 132 + row] = v.w;
        }
        __syncthreads();

#pragma unroll
        for (int kk = 0; kk < BK; kk++) {
            float4 xa = *reinterpret_cast<const float4*>(&Xs[kk * 132 + tr * 8 + 0]);
            float4 xb = *reinterpret_cast<const float4*>(&Xs[kk * 132 + tr * 8 + 4]);
            float4 wv = *reinterpret_cast<const float4*>(&Ws[(k0 + kk) * CFP + tc * 4]);
            float xr[8] = {xa.x, xa.y, xa.z, xa.w, xb.x, xb.y, xb.z, xb.w};
#pragma unroll
            for (int i = 0; i < 8; i++) {
                acc[i][0] += xr[i] * wv.x;
                acc[i][1] += xr[i] * wv.y;
                acc[i][2] += xr[i] * wv.z;
                acc[i][3] += xr[i] * wv.w;
            }
        }
        __syncthreads();
    }

    if (tc * 4 < CF) {
#pragma unroll
        for (int i = 0; i < 8; i++) {
            int r = bm + tr * 8 + i;
            if (r >= N) break;
            float4 v = make_float4(acc[i][0] + bcs[tc * 4 + 0],
                                   acc[i][1] + bcs[tc * 4 + 1],
                                   acc[i][2] + bcs[tc * 4 + 2],
                                   acc[i][3] + bcs[tc * 4 + 3]);
            *reinterpret_cast<float4*>(out + (size_t)r * CF + tc * 4) = v;
        }
    }
}

// ------------------------------------------------------------------ launcher
extern "C" void kernel_launch(void* const* d_in, const int* in_sizes, int n_in,
                              void* d_out, int out_size) {
    const float* x  = (const float*)d_in[0];
    const int*   ei = (const int*)d_in[1];     // int32 (JAX x64-disabled)
    const float* W1 = (const float*)d_in[2];
    const float* b1 = (const float*)d_in[3];
    const float* W2 = (const float*)d_in[4];
    const float* b2 = (const float*)d_in[5];
    const float* Wc = (const float*)d_in[6];
    const float* bc = (const float*)d_in[7];
    float*       out = (float*)d_out;

    const int Hdim = in_sizes[3];             // 64
    const int Fin  = in_sizes[2] / Hdim;      // 128
    const int N    = in_sizes[0] / Fin;       // 100000
    const int E    = in_sizes[1] / 2;         // 1000000
    (void)Hdim; (void)n_in; (void)out_size;

    const int TPB = 256;
    int e4Blk = ((E + 3) / 4 + TPB - 1) / TPB;
    int gBlk  = (N + BM - 1) / BM;
    int sBlk  = (N + 1023) / 1024;            // 98 (all resident -> lookback safe)
    long long gatThreads = (long long)((N + 1) / 2) * 32;
    int gatBlk = (int)((gatThreads + TPB - 1) / TPB);

    // CSR build: count -> fused lookback scan -> atomic-free fill
    k_count<<<e4Blk, TPB>>>(ei, E, N);
    k_scan<<<sBlk, 256>>>(N, E);
    k_fill<<<e4Blk, TPB>>>(ei, E);

    // layer 1: A' = (x@W1)*dinv (fp16) ; B = gather(A')
    k_gemm_tc<128, true><<<gBlk, TPB>>>(x, W1, nullptr, N);
    k_gather<<<gatBlk, TPB>>>(N);

    // layer 2: A' = (relu(B+b1)@W2)*dinv (fp16) ; B = gather(A')
    k_gemm_tc<64, false><<<gBlk, TPB>>>(nullptr, W2, b1, N);
    k_gather<<<gatBlk, TPB>>>(N);

    // classifier (tiled, fuses relu(B + b2))
    k_final<<<gBlk, 192>>>(b2, Wc, bc, out, N);
}